// round 5
// baseline (speedup 1.0000x reference)
#include <cuda_runtime.h>
#include <cstdint>

// Problem constants
#define BATCH  2
#define T_SEQ  2048
#define WID    1024
#define HEADS  16
#define CH     64
#define W3     3072
#define MROWS  (BATCH * T_SEQ)   // 4096

// Scratch (allocation-free rule: use __device__ globals)
__device__ float g_qkv [BATCH * T_SEQ * W3];    // 48 MB
__device__ float g_attn[BATCH * T_SEQ * WID];   // 16 MB
__device__ float g_kmean[BATCH * HEADS * CH];
__device__ float g_pos [BATCH * T_SEQ];
__device__ float g_aw  [BATCH * T_SEQ];

// ---------------------------------------------------------------------------
// mma.sync m16n8k8 tf32 helpers (plain PTX — legal in compute_103 PTX)
// ---------------------------------------------------------------------------
__device__ __forceinline__ void mma_tf32(float* c, const float* a, const float* b)
{
    asm volatile(
        "mma.sync.aligned.m16n8k8.row.col.f32.tf32.tf32.f32 "
        "{%0,%1,%2,%3}, {%4,%5,%6,%7}, {%8,%9}, {%0,%1,%2,%3};"
        : "+f"(c[0]), "+f"(c[1]), "+f"(c[2]), "+f"(c[3])
        : "r"(__float_as_uint(a[0])), "r"(__float_as_uint(a[1])),
          "r"(__float_as_uint(a[2])), "r"(__float_as_uint(a[3])),
          "r"(__float_as_uint(b[0])), "r"(__float_as_uint(b[1])));
}

// fp32 -> tf32 round-to-nearest (value kept in fp32 container)
__device__ __forceinline__ float f2tf32(float x) {
    uint32_t u;
    asm("cvt.rna.tf32.f32 %0, %1;" : "=r"(u) : "f"(x));
    return __uint_as_float(u);
}

// Fragment loaders. lane decomposed as gid = lane>>2 (0..7), tig = lane&3.
// A (m16 x k8), row-major in smem with row stride SA:
//   a0=[r+gid][k+tig] a1=[r+gid+8][k+tig] a2=[r+gid][k+tig+4] a3=[r+gid+8][k+tig+4]
__device__ __forceinline__ void frag_a(float* a, const float* S, int SA,
                                       int r, int k, int gid, int tig)
{
    const float* p0 = S + (r + gid) * SA + k + tig;
    const float* p1 = S + (r + gid + 8) * SA + k + tig;
    a[0] = p0[0]; a[1] = p1[0]; a[2] = p0[4]; a[3] = p1[4];
}
// B (k8 x n8), stored [k][n] with row stride SB:
//   b0=[k+tig][n+gid]  b1=[k+tig+4][n+gid]
__device__ __forceinline__ void frag_b(float* b, const float* S, int SB,
                                       int k, int n, int gid, int tig)
{
    b[0] = S[(k + tig) * SB + n + gid];
    b[1] = S[(k + tig + 4) * SB + n + gid];
}

// ---------------------------------------------------------------------------
// Tensor-core GEMM (3xTF32 via mma.sync): C[M,N] = A[M,K] @ B[K,N] + bias[N]
// CTA tile 128x128, K-chunk 32, 256 threads = 8 warps (4 M x 2 N),
// warp tile 32x64. Smem strides padded for conflict-free fragment loads.
// (VALIDATED in R4 — unchanged.)
// ---------------------------------------------------------------------------
static constexpr int GA_S = 36;    // A smem row stride (floats)
static constexpr int GB_S = 136;   // B smem row stride (floats)
static constexpr int G_AH = 0;
static constexpr int G_AL = 128 * GA_S;              // 4608
static constexpr int G_BH = 2 * 128 * GA_S;          // 9216
static constexpr int G_BL = G_BH + 32 * GB_S;        // 13568
static constexpr int G_TOT = (G_BL + 32 * GB_S) * 4; // 71680 bytes

__global__ __launch_bounds__(256) void gemm_tc(
    const float* __restrict__ A, const float* __restrict__ B,
    const float* __restrict__ bias, float* __restrict__ C,
    int N, int K)
{
    extern __shared__ float sm[];
    float* Ah = sm + G_AH;
    float* Al = sm + G_AL;
    float* Bh = sm + G_BH;
    float* Bl = sm + G_BL;

    const int tid = threadIdx.x;
    const int wid = tid >> 5;
    const int lane = tid & 31;
    const int gid = lane >> 2, tig = lane & 3;
    const int wm = (wid >> 1) * 32;   // warp row offset in tile
    const int wn = (wid & 1) * 64;    // warp col offset in tile
    const int row0 = blockIdx.y * 128;
    const int col0 = blockIdx.x * 128;

    // stagers
    const int ar = tid >> 1;            // 0..127
    const int ak = (tid & 1) * 16;      // 0 or 16
    const int bk = tid >> 3;            // 0..31
    const int bn = (tid & 7) * 16;      // 0..112

    const float* Ap = A + (size_t)(row0 + ar) * K + ak;
    const float* Bp0 = B + col0 + bn;

    float c[2][8][4];
    #pragma unroll
    for (int i = 0; i < 2; i++)
        #pragma unroll
        for (int j = 0; j < 8; j++)
            #pragma unroll
            for (int q = 0; q < 4; q++) c[i][j][q] = 0.f;

    for (int kc = 0; kc < K; kc += 32) {
        __syncthreads();
        // stage A (128x32) hi/lo
        #pragma unroll
        for (int i = 0; i < 4; i++) {
            float4 v = *(const float4*)(Ap + kc + i * 4);
            float4 h, l;
            h.x = f2tf32(v.x); l.x = f2tf32(v.x - h.x);
            h.y = f2tf32(v.y); l.y = f2tf32(v.y - h.y);
            h.z = f2tf32(v.z); l.z = f2tf32(v.z - h.z);
            h.w = f2tf32(v.w); l.w = f2tf32(v.w - h.w);
            *(float4*)(Ah + ar * GA_S + ak + i * 4) = h;
            *(float4*)(Al + ar * GA_S + ak + i * 4) = l;
        }
        // stage B (32x128) hi/lo
        {
            const float* Bp = Bp0 + (size_t)(kc + bk) * N;
            #pragma unroll
            for (int i = 0; i < 4; i++) {
                float4 v = *(const float4*)(Bp + i * 4);
                float4 h, l;
                h.x = f2tf32(v.x); l.x = f2tf32(v.x - h.x);
                h.y = f2tf32(v.y); l.y = f2tf32(v.y - h.y);
                h.z = f2tf32(v.z); l.z = f2tf32(v.z - h.z);
                h.w = f2tf32(v.w); l.w = f2tf32(v.w - h.w);
                *(float4*)(Bh + bk * GB_S + bn + i * 4) = h;
                *(float4*)(Bl + bk * GB_S + bn + i * 4) = l;
            }
        }
        __syncthreads();

        #pragma unroll
        for (int ks = 0; ks < 4; ks++) {
            float ah[2][4], al[2][4];
            frag_a(ah[0], Ah, GA_S, wm,      ks * 8, gid, tig);
            frag_a(ah[1], Ah, GA_S, wm + 16, ks * 8, gid, tig);
            frag_a(al[0], Al, GA_S, wm,      ks * 8, gid, tig);
            frag_a(al[1], Al, GA_S, wm + 16, ks * 8, gid, tig);
            #pragma unroll
            for (int j = 0; j < 8; j++) {
                float bh[2], bl[2];
                frag_b(bh, Bh, GB_S, ks * 8, wn + j * 8, gid, tig);
                frag_b(bl, Bl, GB_S, ks * 8, wn + j * 8, gid, tig);
                #pragma unroll
                for (int i = 0; i < 2; i++) {
                    mma_tf32(c[i][j], ah[i], bh);
                    mma_tf32(c[i][j], ah[i], bl);
                    mma_tf32(c[i][j], al[i], bh);
                }
            }
        }
    }

    // epilogue: c frags + bias -> gmem (float2 per fragment half-row)
    #pragma unroll
    for (int i = 0; i < 2; i++) {
        const int r0 = row0 + wm + i * 16 + gid;
        #pragma unroll
        for (int j = 0; j < 8; j++) {
            const int col = col0 + wn + j * 8 + 2 * tig;
            float2 bv = *(const float2*)&bias[col];
            float2 o0 = make_float2(c[i][j][0] + bv.x, c[i][j][1] + bv.y);
            float2 o1 = make_float2(c[i][j][2] + bv.x, c[i][j][3] + bv.y);
            *(float2*)&C[(size_t)r0 * N + col]       = o0;
            *(float2*)&C[(size_t)(r0 + 8) * N + col] = o1;
        }
    }
}

// ---------------------------------------------------------------------------
// k_mean[b,h,c] = mean over t of k[b,t,h,c]. One block per (b,h).
// ---------------------------------------------------------------------------
__global__ __launch_bounds__(256) void kmean_kernel()
{
    const int bh = blockIdx.x;
    const int b = bh >> 4, h = bh & 15;
    const int c  = threadIdx.x & 63;
    const int tg = threadIdx.x >> 6;   // 0..3
    const float* base = g_qkv + (size_t)b * T_SEQ * W3 + h * 192 + CH + c;
    float s = 0.f;
    for (int t = tg; t < T_SEQ; t += 4) s += base[(size_t)t * W3];
    __shared__ float red[4][64];
    red[tg][c] = s;
    __syncthreads();
    if (tg == 0) {
        float tot = red[0][c] + red[1][c] + red[2][c] + red[3][c];
        g_kmean[bh * CH + c] = tot * (1.f / (float)T_SEQ);
    }
}

// ---------------------------------------------------------------------------
// pos[b,t] = (1/8) * sum_{h,c} q[b,t,h,c] * k_mean[b,h,c].  One block per (b,t).
// ---------------------------------------------------------------------------
__global__ __launch_bounds__(256) void pos_kernel()
{
    const int bt = blockIdx.x;
    const int b  = bt >> 11;
    const float* qb = g_qkv + (size_t)bt * W3;
    const float* km = g_kmean + b * WID;
    float s = 0.f;
    for (int j = threadIdx.x; j < WID; j += 256) {
        const int h = j >> 6, c = j & 63;
        s += qb[h * 192 + c] * km[j];
    }
    #pragma unroll
    for (int msk = 16; msk; msk >>= 1) s += __shfl_xor_sync(0xffffffffu, s, msk);
    __shared__ float red[8];
    if ((threadIdx.x & 31) == 0) red[threadIdx.x >> 5] = s;
    __syncthreads();
    if (threadIdx.x == 0) {
        float t = 0.f;
        #pragma unroll
        for (int w = 0; w < 8; w++) t += red[w];
        g_pos[bt] = t * 0.125f;
    }
}

// ---------------------------------------------------------------------------
// aw[b,t] = (pos - min) / (max - min + 1e-6).  One block per batch.
// ---------------------------------------------------------------------------
__global__ __launch_bounds__(256) void aw_kernel()
{
    const int b = blockIdx.x;
    const int tid = threadIdx.x;
    float vals[8];
    float mn = 1e30f, mx = -1e30f;
    #pragma unroll
    for (int k = 0; k < 8; k++) {
        float v = g_pos[b * T_SEQ + tid + 256 * k];
        vals[k] = v;
        mn = fminf(mn, v);
        mx = fmaxf(mx, v);
    }
    __shared__ float smn[256], smx[256];
    smn[tid] = mn; smx[tid] = mx;
    __syncthreads();
    for (int s = 128; s; s >>= 1) {
        if (tid < s) {
            smn[tid] = fminf(smn[tid], smn[tid + s]);
            smx[tid] = fmaxf(smx[tid], smx[tid + s]);
        }
        __syncthreads();
    }
    const float gmn = smn[0];
    const float inv = 1.f / (smx[0] - smn[0] + 1e-6f);
    #pragma unroll
    for (int k = 0; k < 8; k++)
        g_aw[b * T_SEQ + tid + 256 * k] = (vals[k] - gmn) * inv;
}

// ---------------------------------------------------------------------------
// Flash attention on tensor cores (3xTF32 mma.sync).  FIXED strides vs R3:
// Q/K/P row stride 68 (68 % 32 == 4 -> row-indexed loads conflict-free),
// V row stride 72 (72 % 32 == 8 -> k-indexed B-frag loads conflict-free).
// grid = (T/64, B*H), 128 threads = 4 warps; each warp owns 16 q-rows.
// ---------------------------------------------------------------------------
static constexpr int FA_S  = 68;   // Q/K/P row stride (floats)
static constexpr int FV_S  = 72;   // V row stride (floats)
static constexpr int FO_QH = 0;
static constexpr int FO_QL = FO_QH + 64 * FA_S;        // 4352
static constexpr int FO_KH = FO_QL + 64 * FA_S;        // 8704
static constexpr int FO_KL = FO_KH + 64 * FA_S;        // 13056
static constexpr int FO_VH = FO_KL + 64 * FA_S;        // 17408
static constexpr int FO_VL = FO_VH + 64 * FV_S;        // 22016
static constexpr int FO_P  = FO_VL + 64 * FV_S;        // 26624
static constexpr int FA_PW = 2 * 16 * FA_S;            // per-warp P hi+lo floats
static constexpr int FA_TOT = (FO_P + 4 * FA_PW) * 4;  // 141312 bytes

__global__ __launch_bounds__(128) void flash_attn_tc()
{
    extern __shared__ float sm[];
    float* Qh = sm + FO_QH;
    float* Ql = sm + FO_QL;
    float* Kh = sm + FO_KH;
    float* Kl = sm + FO_KL;
    float* Vh = sm + FO_VH;
    float* Vl = sm + FO_VL;

    const int tid = threadIdx.x;
    const int wid = tid >> 5;
    const int lane = tid & 31;
    const int gid = lane >> 2, tig = lane & 3;
    const int bh  = blockIdx.y;
    const int b = bh >> 4, h = bh & 15;
    const int q0 = blockIdx.x * 64;
    const float* base = g_qkv + (size_t)b * T_SEQ * W3 + h * 192;

    float* Ph = sm + FO_P + wid * FA_PW;
    float* Pl = Ph + 16 * FA_S;

    // Load Q tile (prescale by scale^2 = 1/8, split hi/lo).
    {
        const int r = tid >> 1, c0 = (tid & 1) * 32;
        const float* qrow = base + (size_t)(q0 + r) * W3 + c0;
        #pragma unroll
        for (int i = 0; i < 8; i++) {
            float4 v = *(const float4*)(qrow + i * 4);
            float4 hh, ll;
            float x;
            x = v.x * 0.125f; hh.x = f2tf32(x); ll.x = f2tf32(x - hh.x);
            x = v.y * 0.125f; hh.y = f2tf32(x); ll.y = f2tf32(x - hh.y);
            x = v.z * 0.125f; hh.z = f2tf32(x); ll.z = f2tf32(x - hh.z);
            x = v.w * 0.125f; hh.w = f2tf32(x); ll.w = f2tf32(x - hh.w);
            *(float4*)(Qh + r * FA_S + c0 + i * 4) = hh;
            *(float4*)(Ql + r * FA_S + c0 + i * 4) = ll;
        }
    }

    const int wq = wid * 16;   // warp's q-row offset within tile

    float m0 = -1e30f, m1 = -1e30f, l0 = 0.f, l1 = 0.f;
    float O[8][4];
    #pragma unroll
    for (int j = 0; j < 8; j++)
        #pragma unroll
        for (int q = 0; q < 4; q++) O[j][q] = 0.f;

    for (int t0 = 0; t0 < T_SEQ; t0 += 64) {
        __syncthreads();   // all warps done with K/V of previous chunk
        // stage K (stride 68) and V (stride 72), hi/lo
        {
            const int r = tid >> 1, c0 = (tid & 1) * 32;
            const float* krow = base + (size_t)(t0 + r) * W3 + CH + c0;
            const float* vrow = krow + CH;
            #pragma unroll
            for (int i = 0; i < 8; i++) {
                float4 v = *(const float4*)(krow + i * 4);
                float4 hh, ll;
                hh.x = f2tf32(v.x); ll.x = f2tf32(v.x - hh.x);
                hh.y = f2tf32(v.y); ll.y = f2tf32(v.y - hh.y);
                hh.z = f2tf32(v.z); ll.z = f2tf32(v.z - hh.z);
                hh.w = f2tf32(v.w); ll.w = f2tf32(v.w - hh.w);
                *(float4*)(Kh + r * FA_S + c0 + i * 4) = hh;
                *(float4*)(Kl + r * FA_S + c0 + i * 4) = ll;
                float4 w = *(const float4*)(vrow + i * 4);
                hh.x = f2tf32(w.x); ll.x = f2tf32(w.x - hh.x);
                hh.y = f2tf32(w.y); ll.y = f2tf32(w.y - hh.y);
                hh.z = f2tf32(w.z); ll.z = f2tf32(w.z - hh.z);
                hh.w = f2tf32(w.w); ll.w = f2tf32(w.w - hh.w);
                *(float4*)(Vh + r * FV_S + c0 + i * 4) = hh;
                *(float4*)(Vl + r * FV_S + c0 + i * 4) = ll;
            }
        }
        __syncthreads();

        // ---- S = Q . K^T  (warp: 16 q-rows x 64 t-cols), 3xTF32 ----
        float s[8][4];
        #pragma unroll
        for (int j = 0; j < 8; j++)
            #pragma unroll
            for (int q = 0; q < 4; q++) s[j][q] = 0.f;
        #pragma unroll
        for (int ks = 0; ks < 8; ks++) {
            float ah[4], al[4];
            frag_a(ah, Qh, FA_S, wq, ks * 8, gid, tig);
            frag_a(al, Ql, FA_S, wq, ks * 8, gid, tig);
            #pragma unroll
            for (int j = 0; j < 8; j++) {
                // B[k=c][n=t] = K[t][c]: row-indexed loads, stride 68
                float bhf[2], blf[2];
                bhf[0] = Kh[(j * 8 + gid) * FA_S + ks * 8 + tig];
                bhf[1] = Kh[(j * 8 + gid) * FA_S + ks * 8 + tig + 4];
                blf[0] = Kl[(j * 8 + gid) * FA_S + ks * 8 + tig];
                blf[1] = Kl[(j * 8 + gid) * FA_S + ks * 8 + tig + 4];
                mma_tf32(s[j], ah, bhf);
                mma_tf32(s[j], ah, blf);
                mma_tf32(s[j], al, bhf);
            }
        }

        // ---- online softmax (rows gid and gid+8 of this warp's 16) ----
        float mx0 = -1e30f, mx1 = -1e30f;
        #pragma unroll
        for (int j = 0; j < 8; j++) {
            mx0 = fmaxf(mx0, fmaxf(s[j][0], s[j][1]));
            mx1 = fmaxf(mx1, fmaxf(s[j][2], s[j][3]));
        }
        #pragma unroll
        for (int msk = 1; msk < 4; msk <<= 1) {
            mx0 = fmaxf(mx0, __shfl_xor_sync(0xffffffffu, mx0, msk));
            mx1 = fmaxf(mx1, __shfl_xor_sync(0xffffffffu, mx1, msk));
        }
        const float mn0 = fmaxf(m0, mx0), mn1 = fmaxf(m1, mx1);
        const float al0 = __expf(m0 - mn0), al1 = __expf(m1 - mn1);
        m0 = mn0; m1 = mn1;
        float sum0 = 0.f, sum1 = 0.f;
        #pragma unroll
        for (int j = 0; j < 8; j++) {
            s[j][0] = __expf(s[j][0] - mn0); sum0 += s[j][0];
            s[j][1] = __expf(s[j][1] - mn0); sum0 += s[j][1];
            s[j][2] = __expf(s[j][2] - mn1); sum1 += s[j][2];
            s[j][3] = __expf(s[j][3] - mn1); sum1 += s[j][3];
        }
        #pragma unroll
        for (int msk = 1; msk < 4; msk <<= 1) {
            sum0 += __shfl_xor_sync(0xffffffffu, sum0, msk);
            sum1 += __shfl_xor_sync(0xffffffffu, sum1, msk);
        }
        l0 = l0 * al0 + sum0;
        l1 = l1 * al1 + sum1;
        #pragma unroll
        for (int j = 0; j < 8; j++) {
            O[j][0] *= al0; O[j][1] *= al0;
            O[j][2] *= al1; O[j][3] *= al1;
        }

        // ---- stage P hi/lo into per-warp smem (C-layout -> row-major) ----
        #pragma unroll
        for (int j = 0; j < 8; j++) {
            float h0 = f2tf32(s[j][0]), h1 = f2tf32(s[j][1]);
            float h2 = f2tf32(s[j][2]), h3 = f2tf32(s[j][3]);
            *(float2*)(Ph + gid * FA_S + j * 8 + 2 * tig) = make_float2(h0, h1);
            *(float2*)(Ph + (gid + 8) * FA_S + j * 8 + 2 * tig) = make_float2(h2, h3);
            *(float2*)(Pl + gid * FA_S + j * 8 + 2 * tig) =
                make_float2(s[j][0] - h0, s[j][1] - h1);
            *(float2*)(Pl + (gid + 8) * FA_S + j * 8 + 2 * tig) =
                make_float2(s[j][2] - h2, s[j][3] - h3);
        }
        __syncwarp();

        // ---- O += P . V  (k over 64 keys), 3xTF32 ----
        #pragma unroll
        for (int kt = 0; kt < 8; kt++) {
            float ah[4], al[4];
            frag_a(ah, Ph, FA_S, 0, kt * 8, gid, tig);
            frag_a(al, Pl, FA_S, 0, kt * 8, gid, tig);
            #pragma unroll
            for (int j = 0; j < 8; j++) {
                float bhf[2], blf[2];
                frag_b(bhf, Vh, FV_S, kt * 8, j * 8, gid, tig);
                frag_b(blf, Vl, FV_S, kt * 8, j * 8, gid, tig);
                mma_tf32(O[j], ah, bhf);
                mma_tf32(O[j], ah, blf);
                mma_tf32(O[j], al, bhf);
            }
        }
    }

    // ---- epilogue: normalize, apply adaptive weight, write g_attn ----
    const int t0r = q0 + wq + gid;
    const int t1r = t0r + 8;
    const float w0 = g_aw[b * T_SEQ + t0r] / l0;
    const float w1 = g_aw[b * T_SEQ + t1r] / l1;
    float* o0 = g_attn + (size_t)(b * T_SEQ + t0r) * WID + h * CH;
    float* o1 = g_attn + (size_t)(b * T_SEQ + t1r) * WID + h * CH;
    #pragma unroll
    for (int j = 0; j < 8; j++) {
        const int cc = j * 8 + 2 * tig;
        *(float2*)(o0 + cc) = make_float2(O[j][0] * w0, O[j][1] * w0);
        *(float2*)(o1 + cc) = make_float2(O[j][2] * w1, O[j][3] * w1);
    }
}

// ---------------------------------------------------------------------------
extern "C" void kernel_launch(void* const* d_in, const int* in_sizes, int n_in,
                              void* d_out, int out_size)
{
    const float* x     = (const float*)d_in[0];
    const float* Wqkv  = (const float*)d_in[1];
    const float* bqkv  = (const float*)d_in[2];
    const float* Wproj = (const float*)d_in[3];
    const float* bproj = (const float*)d_in[4];
    float* out = (float*)d_out;

    float *qkv, *attn;
    cudaGetSymbolAddress((void**)&qkv,  g_qkv);
    cudaGetSymbolAddress((void**)&attn, g_attn);

    static bool attr_set = false;
    if (!attr_set) {
        cudaFuncSetAttribute(gemm_tc, cudaFuncAttributeMaxDynamicSharedMemorySize, G_TOT);
        cudaFuncSetAttribute(flash_attn_tc, cudaFuncAttributeMaxDynamicSharedMemorySize, FA_TOT);
        attr_set = true;
    }

    // 1) qkv = x @ W_qkv + b_qkv       (tensor, 3xTF32)
    gemm_tc<<<dim3(W3 / 128, MROWS / 128), 256, G_TOT>>>(x, Wqkv, bqkv, qkv, W3, WID);
    // 2) k_mean
    kmean_kernel<<<BATCH * HEADS, 256>>>();
    // 3) pos = (q . k_mean)/8
    pos_kernel<<<BATCH * T_SEQ, 256>>>();
    // 4) adaptive weight
    aw_kernel<<<BATCH, 256>>>();
    // 5) attention (tensor, fixed strides; applies aw)
    flash_attn_tc<<<dim3(T_SEQ / 64, BATCH * HEADS), 128, FA_TOT>>>();
    // 6) out = attn @ W_proj + b_proj  (tensor, 3xTF32)
    gemm_tc<<<dim3(WID / 128, MROWS / 128), 256, G_TOT>>>(attn, Wproj, bproj, out, WID, WID);
}

// round 6
// speedup vs baseline: 1.7153x; 1.7153x over previous
#include <cuda_runtime.h>
#include <cuda_bf16.h>
#include <cstdint>

// Problem constants
#define BATCH  2
#define T_SEQ  2048
#define WID    1024
#define HEADS  16
#define CH     64
#define W3     3072
#define MROWS  (BATCH * T_SEQ)   // 4096

// Scratch (allocation-free rule: use __device__ globals)
__device__ float g_qkv [BATCH * T_SEQ * W3];    // 48 MB
__device__ float g_attn[BATCH * T_SEQ * WID];   // 16 MB
__device__ float g_kmean[BATCH * HEADS * CH];
__device__ float g_pos [BATCH * T_SEQ];
__device__ float g_aw  [BATCH * T_SEQ];

// ---------------------------------------------------------------------------
// mma.sync helpers (plain PTX — legal in compute_103 PTX)
// ---------------------------------------------------------------------------
__device__ __forceinline__ void mma_tf32(float* c, const float* a, const float* b)
{
    asm volatile(
        "mma.sync.aligned.m16n8k8.row.col.f32.tf32.tf32.f32 "
        "{%0,%1,%2,%3}, {%4,%5,%6,%7}, {%8,%9}, {%0,%1,%2,%3};"
        : "+f"(c[0]), "+f"(c[1]), "+f"(c[2]), "+f"(c[3])
        : "r"(__float_as_uint(a[0])), "r"(__float_as_uint(a[1])),
          "r"(__float_as_uint(a[2])), "r"(__float_as_uint(a[3])),
          "r"(__float_as_uint(b[0])), "r"(__float_as_uint(b[1])));
}

__device__ __forceinline__ void mma_bf16(float* c, const uint32_t* a, const uint32_t* b)
{
    asm volatile(
        "mma.sync.aligned.m16n8k16.row.col.f32.bf16.bf16.f32 "
        "{%0,%1,%2,%3}, {%4,%5,%6,%7}, {%8,%9}, {%0,%1,%2,%3};"
        : "+f"(c[0]), "+f"(c[1]), "+f"(c[2]), "+f"(c[3])
        : "r"(a[0]), "r"(a[1]), "r"(a[2]), "r"(a[3]),
          "r"(b[0]), "r"(b[1]));
}

// fp32 -> tf32 round-to-nearest (value kept in fp32 container)
__device__ __forceinline__ float f2tf32(float x) {
    uint32_t u;
    asm("cvt.rna.tf32.f32 %0, %1;" : "=r"(u) : "f"(x));
    return __uint_as_float(u);
}

// Split two fp32 into packed bf16x2 hi + lo words (low half = first value).
__device__ __forceinline__ void bsplit2(float x0, float x1,
                                        uint32_t& hi, uint32_t& lo)
{
    __nv_bfloat16 h0 = __float2bfloat16(x0);
    __nv_bfloat16 h1 = __float2bfloat16(x1);
    float f0 = __bfloat162float(h0), f1 = __bfloat162float(h1);
    __nv_bfloat16 l0 = __float2bfloat16(x0 - f0);
    __nv_bfloat16 l1 = __float2bfloat16(x1 - f1);
    hi = (uint32_t)__bfloat16_as_ushort(h0) |
         ((uint32_t)__bfloat16_as_ushort(h1) << 16);
    lo = (uint32_t)__bfloat16_as_ushort(l0) |
         ((uint32_t)__bfloat16_as_ushort(l1) << 16);
}

// Fragment loaders. lane decomposed as gid = lane>>2 (0..7), tig = lane&3.
// fp32 A-frag (m16k8):
__device__ __forceinline__ void frag_a(float* a, const float* S, int SA,
                                       int r, int k, int gid, int tig)
{
    const float* p0 = S + (r + gid) * SA + k + tig;
    const float* p1 = S + (r + gid + 8) * SA + k + tig;
    a[0] = p0[0]; a[1] = p1[0]; a[2] = p0[4]; a[3] = p1[4];
}
__device__ __forceinline__ void frag_b(float* b, const float* S, int SB,
                                       int k, int n, int gid, int tig)
{
    b[0] = S[(k + tig) * SB + n + gid];
    b[1] = S[(k + tig + 4) * SB + n + gid];
}
// u32-packed A-frag (m16k16 bf16): kw = k-word offset (k/2)
__device__ __forceinline__ void frag_au(uint32_t* a, const uint32_t* S, int SA,
                                        int r, int kw, int gid, int tig)
{
    const uint32_t* p0 = S + (r + gid) * SA + kw + tig;
    const uint32_t* p1 = S + (r + gid + 8) * SA + kw + tig;
    a[0] = p0[0]; a[1] = p1[0]; a[2] = p0[4]; a[3] = p1[4];
}

// ---------------------------------------------------------------------------
// Tensor-core GEMM (3xTF32 via mma.sync): VALIDATED in R4 — unchanged.
// ---------------------------------------------------------------------------
static constexpr int GA_S = 36;
static constexpr int GB_S = 136;
static constexpr int G_AH = 0;
static constexpr int G_AL = 128 * GA_S;
static constexpr int G_BH = 2 * 128 * GA_S;
static constexpr int G_BL = G_BH + 32 * GB_S;
static constexpr int G_TOT = (G_BL + 32 * GB_S) * 4; // 71680 bytes

__global__ __launch_bounds__(256) void gemm_tc(
    const float* __restrict__ A, const float* __restrict__ B,
    const float* __restrict__ bias, float* __restrict__ C,
    int N, int K)
{
    extern __shared__ float sm[];
    float* Ah = sm + G_AH;
    float* Al = sm + G_AL;
    float* Bh = sm + G_BH;
    float* Bl = sm + G_BL;

    const int tid = threadIdx.x;
    const int wid = tid >> 5;
    const int lane = tid & 31;
    const int gid = lane >> 2, tig = lane & 3;
    const int wm = (wid >> 1) * 32;
    const int wn = (wid & 1) * 64;
    const int row0 = blockIdx.y * 128;
    const int col0 = blockIdx.x * 128;

    const int ar = tid >> 1;
    const int ak = (tid & 1) * 16;
    const int bk = tid >> 3;
    const int bn = (tid & 7) * 16;

    const float* Ap = A + (size_t)(row0 + ar) * K + ak;
    const float* Bp0 = B + col0 + bn;

    float c[2][8][4];
    #pragma unroll
    for (int i = 0; i < 2; i++)
        #pragma unroll
        for (int j = 0; j < 8; j++)
            #pragma unroll
            for (int q = 0; q < 4; q++) c[i][j][q] = 0.f;

    for (int kc = 0; kc < K; kc += 32) {
        __syncthreads();
        #pragma unroll
        for (int i = 0; i < 4; i++) {
            float4 v = *(const float4*)(Ap + kc + i * 4);
            float4 h, l;
            h.x = f2tf32(v.x); l.x = f2tf32(v.x - h.x);
            h.y = f2tf32(v.y); l.y = f2tf32(v.y - h.y);
            h.z = f2tf32(v.z); l.z = f2tf32(v.z - h.z);
            h.w = f2tf32(v.w); l.w = f2tf32(v.w - h.w);
            *(float4*)(Ah + ar * GA_S + ak + i * 4) = h;
            *(float4*)(Al + ar * GA_S + ak + i * 4) = l;
        }
        {
            const float* Bp = Bp0 + (size_t)(kc + bk) * N;
            #pragma unroll
            for (int i = 0; i < 4; i++) {
                float4 v = *(const float4*)(Bp + i * 4);
                float4 h, l;
                h.x = f2tf32(v.x); l.x = f2tf32(v.x - h.x);
                h.y = f2tf32(v.y); l.y = f2tf32(v.y - h.y);
                h.z = f2tf32(v.z); l.z = f2tf32(v.z - h.z);
                h.w = f2tf32(v.w); l.w = f2tf32(v.w - h.w);
                *(float4*)(Bh + bk * GB_S + bn + i * 4) = h;
                *(float4*)(Bl + bk * GB_S + bn + i * 4) = l;
            }
        }
        __syncthreads();

        #pragma unroll
        for (int ks = 0; ks < 4; ks++) {
            float ah[2][4], al[2][4];
            frag_a(ah[0], Ah, GA_S, wm,      ks * 8, gid, tig);
            frag_a(ah[1], Ah, GA_S, wm + 16, ks * 8, gid, tig);
            frag_a(al[0], Al, GA_S, wm,      ks * 8, gid, tig);
            frag_a(al[1], Al, GA_S, wm + 16, ks * 8, gid, tig);
            #pragma unroll
            for (int j = 0; j < 8; j++) {
                float bh[2], bl[2];
                frag_b(bh, Bh, GB_S, ks * 8, wn + j * 8, gid, tig);
                frag_b(bl, Bl, GB_S, ks * 8, wn + j * 8, gid, tig);
                #pragma unroll
                for (int i = 0; i < 2; i++) {
                    mma_tf32(c[i][j], ah[i], bh);
                    mma_tf32(c[i][j], ah[i], bl);
                    mma_tf32(c[i][j], al[i], bh);
                }
            }
        }
    }

    #pragma unroll
    for (int i = 0; i < 2; i++) {
        const int r0 = row0 + wm + i * 16 + gid;
        #pragma unroll
        for (int j = 0; j < 8; j++) {
            const int col = col0 + wn + j * 8 + 2 * tig;
            float2 bv = *(const float2*)&bias[col];
            float2 o0 = make_float2(c[i][j][0] + bv.x, c[i][j][1] + bv.y);
            float2 o1 = make_float2(c[i][j][2] + bv.x, c[i][j][3] + bv.y);
            *(float2*)&C[(size_t)r0 * N + col]       = o0;
            *(float2*)&C[(size_t)(r0 + 8) * N + col] = o1;
        }
    }
}

// ---------------------------------------------------------------------------
// k_mean / pos / aw — unchanged
// ---------------------------------------------------------------------------
__global__ __launch_bounds__(256) void kmean_kernel()
{
    const int bh = blockIdx.x;
    const int b = bh >> 4, h = bh & 15;
    const int c  = threadIdx.x & 63;
    const int tg = threadIdx.x >> 6;
    const float* base = g_qkv + (size_t)b * T_SEQ * W3 + h * 192 + CH + c;
    float s = 0.f;
    for (int t = tg; t < T_SEQ; t += 4) s += base[(size_t)t * W3];
    __shared__ float red[4][64];
    red[tg][c] = s;
    __syncthreads();
    if (tg == 0) {
        float tot = red[0][c] + red[1][c] + red[2][c] + red[3][c];
        g_kmean[bh * CH + c] = tot * (1.f / (float)T_SEQ);
    }
}

__global__ __launch_bounds__(256) void pos_kernel()
{
    const int bt = blockIdx.x;
    const int b  = bt >> 11;
    const float* qb = g_qkv + (size_t)bt * W3;
    const float* km = g_kmean + b * WID;
    float s = 0.f;
    for (int j = threadIdx.x; j < WID; j += 256) {
        const int h = j >> 6, c = j & 63;
        s += qb[h * 192 + c] * km[j];
    }
    #pragma unroll
    for (int msk = 16; msk; msk >>= 1) s += __shfl_xor_sync(0xffffffffu, s, msk);
    __shared__ float red[8];
    if ((threadIdx.x & 31) == 0) red[threadIdx.x >> 5] = s;
    __syncthreads();
    if (threadIdx.x == 0) {
        float t = 0.f;
        #pragma unroll
        for (int w = 0; w < 8; w++) t += red[w];
        g_pos[bt] = t * 0.125f;
    }
}

__global__ __launch_bounds__(256) void aw_kernel()
{
    const int b = blockIdx.x;
    const int tid = threadIdx.x;
    float vals[8];
    float mn = 1e30f, mx = -1e30f;
    #pragma unroll
    for (int k = 0; k < 8; k++) {
        float v = g_pos[b * T_SEQ + tid + 256 * k];
        vals[k] = v;
        mn = fminf(mn, v);
        mx = fmaxf(mx, v);
    }
    __shared__ float smn[256], smx[256];
    smn[tid] = mn; smx[tid] = mx;
    __syncthreads();
    for (int s = 128; s; s >>= 1) {
        if (tid < s) {
            smn[tid] = fminf(smn[tid], smn[tid + s]);
            smx[tid] = fmaxf(smx[tid], smx[tid + s]);
        }
        __syncthreads();
    }
    const float gmn = smn[0];
    const float inv = 1.f / (smx[0] - smn[0] + 1e-6f);
    #pragma unroll
    for (int k = 0; k < 8; k++)
        g_aw[b * T_SEQ + tid + 256 * k] = (vals[k] - gmn) * inv;
}

// ---------------------------------------------------------------------------
// Flash attention v2 — bf16x3 (2-way split, 3 products) on m16n8k16 mma.sync.
// 256 threads / 8 warps, Q-tile 128 rows (16 per warp), K-chunk 64.
// All operands packed bf16x2 (u32 word = two consecutive k-elements).
// Strides (u32): Q/K/P 36 (banks 4g+t, conflict-free), V 72 (banks 8t+g).
// Smem 110592 B -> 2 CTAs/SM (16 warps/SM).
// ---------------------------------------------------------------------------
static constexpr int FQS = 36;   // Q/K/P u32 row stride
static constexpr int FVS = 72;   // V u32 row stride
static constexpr int U_QH = 0;
static constexpr int U_QL = U_QH + 128 * FQS;   // 4608
static constexpr int U_KH = U_QL + 128 * FQS;   // 9216
static constexpr int U_KL = U_KH + 64 * FQS;    // 11520
static constexpr int U_VH = U_KL + 64 * FQS;    // 13824
static constexpr int U_VL = U_VH + 32 * FVS;    // 16128
static constexpr int U_P  = U_VL + 32 * FVS;    // 18432
static constexpr int U_PW = 2 * 16 * FQS;       // per-warp P hi+lo (1152 u32)
static constexpr int FA_TOT = (U_P + 8 * U_PW) * 4;  // 110592 bytes

__global__ __launch_bounds__(256, 2) void flash_attn_tc()
{
    extern __shared__ uint32_t smu[];
    uint32_t* QH = smu + U_QH;
    uint32_t* QL = smu + U_QL;
    uint32_t* KH = smu + U_KH;
    uint32_t* KL = smu + U_KL;
    uint32_t* VH = smu + U_VH;
    uint32_t* VL = smu + U_VL;

    const int tid = threadIdx.x;
    const int wid = tid >> 5;
    const int lane = tid & 31;
    const int gid = lane >> 2, tig = lane & 3;
    const int bh  = blockIdx.y;
    const int b = bh >> 4, h = bh & 15;
    const int q0 = blockIdx.x * 128;
    const float* base = g_qkv + (size_t)b * T_SEQ * W3 + h * 192;

    uint32_t* Ph = smu + U_P + wid * U_PW;
    uint32_t* Pl = Ph + 16 * FQS;

    // ---- Load Q tile (128 rows): prescale 1/8, bf16-split, pack pairs ----
    {
        const int r = tid >> 1, c0 = (tid & 1) * 32;
        const float* qrow = base + (size_t)(q0 + r) * W3 + c0;
        #pragma unroll
        for (int i = 0; i < 8; i++) {
            float4 v = *(const float4*)(qrow + i * 4);
            uint32_t h0, l0, h1, l1;
            bsplit2(v.x * 0.125f, v.y * 0.125f, h0, l0);
            bsplit2(v.z * 0.125f, v.w * 0.125f, h1, l1);
            const int w = r * FQS + c0 / 2 + i * 2;
            QH[w] = h0; QH[w + 1] = h1;
            QL[w] = l0; QL[w + 1] = l1;
        }
    }

    const int wq = wid * 16;   // warp's q-row offset within tile

    float m0 = -1e30f, m1 = -1e30f, l0v = 0.f, l1v = 0.f;
    float O[8][4];
    #pragma unroll
    for (int j = 0; j < 8; j++)
        #pragma unroll
        for (int q = 0; q < 4; q++) O[j][q] = 0.f;

    for (int t0 = 0; t0 < T_SEQ; t0 += 64) {
        __syncthreads();   // all warps done with previous K/V
        // ---- stage K: 64 keys x 64 ch, packed along ch ----
        {
            const int r = tid >> 2, c0 = (tid & 3) * 16;
            const float* krow = base + (size_t)(t0 + r) * W3 + CH + c0;
            #pragma unroll
            for (int i = 0; i < 4; i++) {
                float4 v = *(const float4*)(krow + i * 4);
                uint32_t h0, l0, h1, l1;
                bsplit2(v.x, v.y, h0, l0);
                bsplit2(v.z, v.w, h1, l1);
                const int w = r * FQS + c0 / 2 + i * 2;
                KH[w] = h0; KH[w + 1] = h1;
                KL[w] = l0; KL[w + 1] = l1;
            }
        }
        // ---- stage V: packed along keys: word = (V[2kp][c], V[2kp+1][c]) ----
        {
            const int kp = tid >> 3, c0 = (tid & 7) * 8;
            const float* v0 = base + (size_t)(t0 + 2 * kp) * W3 + 2 * CH + c0;
            const float* v1 = v0 + W3;
            float4 a0 = *(const float4*)(v0);
            float4 a1 = *(const float4*)(v0 + 4);
            float4 b0 = *(const float4*)(v1);
            float4 b1 = *(const float4*)(v1 + 4);
            const float va[8] = {a0.x, a0.y, a0.z, a0.w, a1.x, a1.y, a1.z, a1.w};
            const float vb[8] = {b0.x, b0.y, b0.z, b0.w, b1.x, b1.y, b1.z, b1.w};
            #pragma unroll
            for (int c = 0; c < 8; c++) {
                uint32_t hi, lo;
                bsplit2(va[c], vb[c], hi, lo);
                VH[kp * FVS + c0 + c] = hi;
                VL[kp * FVS + c0 + c] = lo;
            }
        }
        __syncthreads();

        // ---- S = Q . K^T  (16 q-rows x 64 keys per warp), bf16x3 ----
        float s[8][4];
        #pragma unroll
        for (int j = 0; j < 8; j++)
            #pragma unroll
            for (int q = 0; q < 4; q++) s[j][q] = 0.f;
        #pragma unroll
        for (int ks = 0; ks < 4; ks++) {          // 4 x k16 over 64 channels
            uint32_t ah[4], al[4];
            frag_au(ah, QH, FQS, wq, ks * 8, gid, tig);
            frag_au(al, QL, FQS, wq, ks * 8, gid, tig);
            #pragma unroll
            for (int j = 0; j < 8; j++) {
                const int krow = (j * 8 + gid) * FQS + ks * 8 + tig;
                uint32_t bh[2], bl[2];
                bh[0] = KH[krow]; bh[1] = KH[krow + 4];
                bl[0] = KL[krow]; bl[1] = KL[krow + 4];
                mma_bf16(s[j], ah, bh);
                mma_bf16(s[j], ah, bl);
                mma_bf16(s[j], al, bh);
            }
        }

        // ---- online softmax (rows gid and gid+8) ----
        float mx0 = -1e30f, mx1 = -1e30f;
        #pragma unroll
        for (int j = 0; j < 8; j++) {
            mx0 = fmaxf(mx0, fmaxf(s[j][0], s[j][1]));
            mx1 = fmaxf(mx1, fmaxf(s[j][2], s[j][3]));
        }
        #pragma unroll
        for (int msk = 1; msk < 4; msk <<= 1) {
            mx0 = fmaxf(mx0, __shfl_xor_sync(0xffffffffu, mx0, msk));
            mx1 = fmaxf(mx1, __shfl_xor_sync(0xffffffffu, mx1, msk));
        }
        const float mn0 = fmaxf(m0, mx0), mn1 = fmaxf(m1, mx1);
        const float al0 = __expf(m0 - mn0), al1 = __expf(m1 - mn1);
        m0 = mn0; m1 = mn1;
        float sum0 = 0.f, sum1 = 0.f;
        #pragma unroll
        for (int j = 0; j < 8; j++) {
            s[j][0] = __expf(s[j][0] - mn0); sum0 += s[j][0];
            s[j][1] = __expf(s[j][1] - mn0); sum0 += s[j][1];
            s[j][2] = __expf(s[j][2] - mn1); sum1 += s[j][2];
            s[j][3] = __expf(s[j][3] - mn1); sum1 += s[j][3];
        }
        #pragma unroll
        for (int msk = 1; msk < 4; msk <<= 1) {
            sum0 += __shfl_xor_sync(0xffffffffu, sum0, msk);
            sum1 += __shfl_xor_sync(0xffffffffu, sum1, msk);
        }
        l0v = l0v * al0 + sum0;
        l1v = l1v * al1 + sum1;
        #pragma unroll
        for (int j = 0; j < 8; j++) {
            O[j][0] *= al0; O[j][1] *= al0;
            O[j][2] *= al1; O[j][3] *= al1;
        }

        // ---- stage P (per-warp private): pack key-pairs, bf16 split ----
        // c0/c1 are keys j*8+2tig, j*8+2tig+1 (row gid) -> one u32 word.
        #pragma unroll
        for (int j = 0; j < 8; j++) {
            uint32_t hi, lo;
            bsplit2(s[j][0], s[j][1], hi, lo);
            Ph[gid * FQS + j * 4 + tig] = hi;
            Pl[gid * FQS + j * 4 + tig] = lo;
            bsplit2(s[j][2], s[j][3], hi, lo);
            Ph[(gid + 8) * FQS + j * 4 + tig] = hi;
            Pl[(gid + 8) * FQS + j * 4 + tig] = lo;
        }
        __syncwarp();

        // ---- O += P . V  (k over 64 keys = 4 x k16), bf16x3 ----
        #pragma unroll
        for (int kt = 0; kt < 4; kt++) {
            uint32_t ph[4], pl[4];
            frag_au(ph, Ph, FQS, 0, kt * 8, gid, tig);
            frag_au(pl, Pl, FQS, 0, kt * 8, gid, tig);
            #pragma unroll
            for (int j = 0; j < 8; j++) {
                const int vrow = (kt * 8 + tig) * FVS + j * 8 + gid;
                uint32_t bh[2], bl[2];
                bh[0] = VH[vrow]; bh[1] = VH[vrow + 4 * FVS];
                bl[0] = VL[vrow]; bl[1] = VL[vrow + 4 * FVS];
                mma_bf16(O[j], ph, bh);
                mma_bf16(O[j], ph, bl);
                mma_bf16(O[j], pl, bh);
            }
        }
    }

    // ---- epilogue: normalize, apply adaptive weight, write g_attn ----
    const int t0r = q0 + wq + gid;
    const int t1r = t0r + 8;
    const float w0 = g_aw[b * T_SEQ + t0r] / l0v;
    const float w1 = g_aw[b * T_SEQ + t1r] / l1v;
    float* o0 = g_attn + (size_t)(b * T_SEQ + t0r) * WID + h * CH;
    float* o1 = g_attn + (size_t)(b * T_SEQ + t1r) * WID + h * CH;
    #pragma unroll
    for (int j = 0; j < 8; j++) {
        const int cc = j * 8 + 2 * tig;
        *(float2*)(o0 + cc) = make_float2(O[j][0] * w0, O[j][1] * w0);
        *(float2*)(o1 + cc) = make_float2(O[j][2] * w1, O[j][3] * w1);
    }
}

// ---------------------------------------------------------------------------
extern "C" void kernel_launch(void* const* d_in, const int* in_sizes, int n_in,
                              void* d_out, int out_size)
{
    const float* x     = (const float*)d_in[0];
    const float* Wqkv  = (const float*)d_in[1];
    const float* bqkv  = (const float*)d_in[2];
    const float* Wproj = (const float*)d_in[3];
    const float* bproj = (const float*)d_in[4];
    float* out = (float*)d_out;

    float *qkv, *attn;
    cudaGetSymbolAddress((void**)&qkv,  g_qkv);
    cudaGetSymbolAddress((void**)&attn, g_attn);

    static bool attr_set = false;
    if (!attr_set) {
        cudaFuncSetAttribute(gemm_tc, cudaFuncAttributeMaxDynamicSharedMemorySize, G_TOT);
        cudaFuncSetAttribute(flash_attn_tc, cudaFuncAttributeMaxDynamicSharedMemorySize, FA_TOT);
        attr_set = true;
    }

    // 1) qkv = x @ W_qkv + b_qkv       (tensor, 3xTF32 — validated)
    gemm_tc<<<dim3(W3 / 128, MROWS / 128), 256, G_TOT>>>(x, Wqkv, bqkv, qkv, W3, WID);
    // 2) k_mean
    kmean_kernel<<<BATCH * HEADS, 256>>>();
    // 3) pos = (q . k_mean)/8
    pos_kernel<<<BATCH * T_SEQ, 256>>>();
    // 4) adaptive weight
    aw_kernel<<<BATCH, 256>>>();
    // 5) attention (tensor, bf16x3, 2 CTAs/SM; applies aw)
    flash_attn_tc<<<dim3(T_SEQ / 128, BATCH * HEADS), 256, FA_TOT>>>();
    // 6) out = attn @ W_proj + b_proj  (tensor, 3xTF32 — validated)
    gemm_tc<<<dim3(WID / 128, MROWS / 128), 256, G_TOT>>>(attn, Wproj, bproj, out, WID, WID);
}

// round 7
// speedup vs baseline: 2.5867x; 1.5080x over previous
#include <cuda_runtime.h>
#include <cuda_bf16.h>
#include <cstdint>

// Problem constants
#define BATCH  2
#define T_SEQ  2048
#define WID    1024
#define HEADS  16
#define CH     64
#define W3     3072
#define MROWS  (BATCH * T_SEQ)   // 4096

// Scratch (allocation-free rule: use __device__ globals)
__device__ float g_qkv [BATCH * T_SEQ * W3];    // 48 MB
__device__ float g_attn[BATCH * T_SEQ * WID];   // 16 MB
__device__ float g_kmean[BATCH * HEADS * CH];
__device__ float g_pos [BATCH * T_SEQ];
__device__ float g_aw  [BATCH * T_SEQ];

// ---------------------------------------------------------------------------
// mma.sync helpers (plain PTX — legal in compute_103 PTX)
// ---------------------------------------------------------------------------
__device__ __forceinline__ void mma_bf16(float* c, const uint32_t* a, const uint32_t* b)
{
    asm volatile(
        "mma.sync.aligned.m16n8k16.row.col.f32.bf16.bf16.f32 "
        "{%0,%1,%2,%3}, {%4,%5,%6,%7}, {%8,%9}, {%0,%1,%2,%3};"
        : "+f"(c[0]), "+f"(c[1]), "+f"(c[2]), "+f"(c[3])
        : "r"(a[0]), "r"(a[1]), "r"(a[2]), "r"(a[3]),
          "r"(b[0]), "r"(b[1]));
}

// Split two fp32 into packed bf16x2 hi + lo words (low half = first value).
__device__ __forceinline__ void bsplit2(float x0, float x1,
                                        uint32_t& hi, uint32_t& lo)
{
    __nv_bfloat16 h0 = __float2bfloat16(x0);
    __nv_bfloat16 h1 = __float2bfloat16(x1);
    float f0 = __bfloat162float(h0), f1 = __bfloat162float(h1);
    __nv_bfloat16 l0 = __float2bfloat16(x0 - f0);
    __nv_bfloat16 l1 = __float2bfloat16(x1 - f1);
    hi = (uint32_t)__bfloat16_as_ushort(h0) |
         ((uint32_t)__bfloat16_as_ushort(h1) << 16);
    lo = (uint32_t)__bfloat16_as_ushort(l0) |
         ((uint32_t)__bfloat16_as_ushort(l1) << 16);
}

// u32-packed A-frag (m16k16 bf16). lane = gid*4+tig; kw = k-word offset (k/2).
// a0=(r+gid, k:2tig..) a1=(r+gid+8, ..) a2=(r+gid, k+8..) a3=(r+gid+8, k+8..)
__device__ __forceinline__ void frag_au(uint32_t* a, const uint32_t* S, int SA,
                                        int r, int kw, int gid, int tig)
{
    const uint32_t* p0 = S + (r + gid) * SA + kw + tig;
    const uint32_t* p1 = S + (r + gid + 8) * SA + kw + tig;
    a[0] = p0[0]; a[1] = p1[0]; a[2] = p0[4]; a[3] = p1[4];
}

// ---------------------------------------------------------------------------
// Tensor-core GEMM, bf16x3 (2-way split, 3 products) on m16n8k16 mma.sync.
// C[M,N] = A[M,K] @ B[K,N] + bias[N].
// CTA tile 128x128, K-chunk 32, 256 threads = 8 warps (4 M x 2 N),
// warp tile 32x64. Operands packed bf16x2 u32 (word = 2 consecutive k).
// A stride 20 u32 (banks 20g+t: distinct), B stride 136 (banks 8t+g: distinct).
// Smem 37888 B.
// ---------------------------------------------------------------------------
static constexpr int BA_S = 20;    // A u32 row stride (16 words + pad)
static constexpr int BB_S = 136;   // B u32 kp-row stride (128 words + pad)
static constexpr int GB_AH = 0;
static constexpr int GB_AL = 128 * BA_S;             // 2560
static constexpr int GB_BH = 2 * 128 * BA_S;         // 5120
static constexpr int GB_BL = GB_BH + 16 * BB_S;      // 7296
static constexpr int G_TOT = (GB_BL + 16 * BB_S) * 4; // 37888 bytes

__global__ __launch_bounds__(256) void gemm_bf16(
    const float* __restrict__ A, const float* __restrict__ B,
    const float* __restrict__ bias, float* __restrict__ C,
    int N, int K)
{
    extern __shared__ uint32_t smu[];
    uint32_t* AH = smu + GB_AH;
    uint32_t* AL = smu + GB_AL;
    uint32_t* BH = smu + GB_BH;
    uint32_t* BL = smu + GB_BL;

    const int tid = threadIdx.x;
    const int wid = tid >> 5;
    const int lane = tid & 31;
    const int gid = lane >> 2, tig = lane & 3;
    const int wm = (wid >> 1) * 32;   // warp row offset in tile
    const int wn = (wid & 1) * 64;    // warp col offset in tile
    const int row0 = blockIdx.y * 128;
    const int col0 = blockIdx.x * 128;

    // stagers
    const int ar  = tid >> 1;           // 0..127
    const int ak  = (tid & 1) * 16;     // float offset 0 or 16
    const int bkp = tid >> 4;           // 0..15 (k-pair row)
    const int bn0 = (tid & 15) * 8;     // 0..120

    const float* Ap  = A + (size_t)(row0 + ar) * K + ak;
    const float* Bp0 = B + col0 + bn0;

    float c[2][8][4];
    #pragma unroll
    for (int i = 0; i < 2; i++)
        #pragma unroll
        for (int j = 0; j < 8; j++)
            #pragma unroll
            for (int q = 0; q < 4; q++) c[i][j][q] = 0.f;

    for (int kc = 0; kc < K; kc += 32) {
        __syncthreads();
        // ---- stage A (128 x 32 fp32 -> 128 x 16 u32 hi/lo) ----
        #pragma unroll
        for (int i = 0; i < 4; i++) {
            float4 v = *(const float4*)(Ap + kc + i * 4);
            uint32_t h0, l0, h1, l1;
            bsplit2(v.x, v.y, h0, l0);
            bsplit2(v.z, v.w, h1, l1);
            const int w = ar * BA_S + ak / 2 + i * 2;
            AH[w] = h0; AH[w + 1] = h1;
            AL[w] = l0; AL[w + 1] = l1;
        }
        // ---- stage B (32 x 128 fp32 -> 16 kp-rows x 128 u32 hi/lo) ----
        {
            const float* Bp = Bp0 + (size_t)(kc + 2 * bkp) * N;
            float4 x0 = *(const float4*)(Bp);
            float4 x1 = *(const float4*)(Bp + 4);
            float4 y0 = *(const float4*)(Bp + N);
            float4 y1 = *(const float4*)(Bp + N + 4);
            const float xa[8] = {x0.x, x0.y, x0.z, x0.w, x1.x, x1.y, x1.z, x1.w};
            const float ya[8] = {y0.x, y0.y, y0.z, y0.w, y1.x, y1.y, y1.z, y1.w};
            #pragma unroll
            for (int cI = 0; cI < 8; cI++) {
                uint32_t hi, lo;
                bsplit2(xa[cI], ya[cI], hi, lo);   // word = (B[k][n], B[k+1][n])
                BH[bkp * BB_S + bn0 + cI] = hi;
                BL[bkp * BB_S + bn0 + cI] = lo;
            }
        }
        __syncthreads();

        // ---- MMA: 2 x k16 steps, bf16x3 ----
        #pragma unroll
        for (int ks = 0; ks < 2; ks++) {
            uint32_t ah[2][4], al_[2][4];
            frag_au(ah[0],  AH, BA_S, wm,      ks * 8, gid, tig);
            frag_au(ah[1],  AH, BA_S, wm + 16, ks * 8, gid, tig);
            frag_au(al_[0], AL, BA_S, wm,      ks * 8, gid, tig);
            frag_au(al_[1], AL, BA_S, wm + 16, ks * 8, gid, tig);
            #pragma unroll
            for (int j = 0; j < 8; j++) {
                const int base = (ks * 8 + tig) * BB_S + wn + j * 8 + gid;
                uint32_t bh[2], bl[2];
                bh[0] = BH[base]; bh[1] = BH[base + 4 * BB_S];
                bl[0] = BL[base]; bl[1] = BL[base + 4 * BB_S];
                #pragma unroll
                for (int i = 0; i < 2; i++) {
                    mma_bf16(c[i][j], ah[i],  bh);
                    mma_bf16(c[i][j], ah[i],  bl);
                    mma_bf16(c[i][j], al_[i], bh);
                }
            }
        }
    }

    // ---- epilogue: c frags + bias -> gmem ----
    #pragma unroll
    for (int i = 0; i < 2; i++) {
        const int r0 = row0 + wm + i * 16 + gid;
        #pragma unroll
        for (int j = 0; j < 8; j++) {
            const int col = col0 + wn + j * 8 + 2 * tig;
            float2 bv = *(const float2*)&bias[col];
            float2 o0 = make_float2(c[i][j][0] + bv.x, c[i][j][1] + bv.y);
            float2 o1 = make_float2(c[i][j][2] + bv.x, c[i][j][3] + bv.y);
            *(float2*)&C[(size_t)r0 * N + col]       = o0;
            *(float2*)&C[(size_t)(r0 + 8) * N + col] = o1;
        }
    }
}

// ---------------------------------------------------------------------------
// k_mean / pos / aw — unchanged
// ---------------------------------------------------------------------------
__global__ __launch_bounds__(256) void kmean_kernel()
{
    const int bh = blockIdx.x;
    const int b = bh >> 4, h = bh & 15;
    const int c  = threadIdx.x & 63;
    const int tg = threadIdx.x >> 6;
    const float* base = g_qkv + (size_t)b * T_SEQ * W3 + h * 192 + CH + c;
    float s = 0.f;
    for (int t = tg; t < T_SEQ; t += 4) s += base[(size_t)t * W3];
    __shared__ float red[4][64];
    red[tg][c] = s;
    __syncthreads();
    if (tg == 0) {
        float tot = red[0][c] + red[1][c] + red[2][c] + red[3][c];
        g_kmean[bh * CH + c] = tot * (1.f / (float)T_SEQ);
    }
}

__global__ __launch_bounds__(256) void pos_kernel()
{
    const int bt = blockIdx.x;
    const int b  = bt >> 11;
    const float* qb = g_qkv + (size_t)bt * W3;
    const float* km = g_kmean + b * WID;
    float s = 0.f;
    for (int j = threadIdx.x; j < WID; j += 256) {
        const int h = j >> 6, c = j & 63;
        s += qb[h * 192 + c] * km[j];
    }
    #pragma unroll
    for (int msk = 16; msk; msk >>= 1) s += __shfl_xor_sync(0xffffffffu, s, msk);
    __shared__ float red[8];
    if ((threadIdx.x & 31) == 0) red[threadIdx.x >> 5] = s;
    __syncthreads();
    if (threadIdx.x == 0) {
        float t = 0.f;
        #pragma unroll
        for (int w = 0; w < 8; w++) t += red[w];
        g_pos[bt] = t * 0.125f;
    }
}

__global__ __launch_bounds__(256) void aw_kernel()
{
    const int b = blockIdx.x;
    const int tid = threadIdx.x;
    float vals[8];
    float mn = 1e30f, mx = -1e30f;
    #pragma unroll
    for (int k = 0; k < 8; k++) {
        float v = g_pos[b * T_SEQ + tid + 256 * k];
        vals[k] = v;
        mn = fminf(mn, v);
        mx = fmaxf(mx, v);
    }
    __shared__ float smn[256], smx[256];
    smn[tid] = mn; smx[tid] = mx;
    __syncthreads();
    for (int s = 128; s; s >>= 1) {
        if (tid < s) {
            smn[tid] = fminf(smn[tid], smn[tid + s]);
            smx[tid] = fmaxf(smx[tid], smx[tid + s]);
        }
        __syncthreads();
    }
    const float gmn = smn[0];
    const float inv = 1.f / (smx[0] - smn[0] + 1e-6f);
    #pragma unroll
    for (int k = 0; k < 8; k++)
        g_aw[b * T_SEQ + tid + 256 * k] = (vals[k] - gmn) * inv;
}

// ---------------------------------------------------------------------------
// Flash attention — bf16x3 on m16n8k16 mma.sync. (VALIDATED in R6 — unchanged)
// 256 threads / 8 warps, Q-tile 128 rows (16 per warp), K-chunk 64.
// Strides (u32): Q/K/P 36 (banks 4g+t), V 72 (banks 8t+g). 2 CTAs/SM.
// ---------------------------------------------------------------------------
static constexpr int FQS = 36;   // Q/K/P u32 row stride
static constexpr int FVS = 72;   // V u32 row stride
static constexpr int U_QH = 0;
static constexpr int U_QL = U_QH + 128 * FQS;   // 4608
static constexpr int U_KH = U_QL + 128 * FQS;   // 9216
static constexpr int U_KL = U_KH + 64 * FQS;    // 11520
static constexpr int U_VH = U_KL + 64 * FQS;    // 13824
static constexpr int U_VL = U_VH + 32 * FVS;    // 16128
static constexpr int U_P  = U_VL + 32 * FVS;    // 18432
static constexpr int U_PW = 2 * 16 * FQS;       // per-warp P hi+lo (1152 u32)
static constexpr int FA_TOT = (U_P + 8 * U_PW) * 4;  // 110592 bytes

__global__ __launch_bounds__(256, 2) void flash_attn_tc()
{
    extern __shared__ uint32_t smu[];
    uint32_t* QH = smu + U_QH;
    uint32_t* QL = smu + U_QL;
    uint32_t* KH = smu + U_KH;
    uint32_t* KL = smu + U_KL;
    uint32_t* VH = smu + U_VH;
    uint32_t* VL = smu + U_VL;

    const int tid = threadIdx.x;
    const int wid = tid >> 5;
    const int lane = tid & 31;
    const int gid = lane >> 2, tig = lane & 3;
    const int bh  = blockIdx.y;
    const int b = bh >> 4, h = bh & 15;
    const int q0 = blockIdx.x * 128;
    const float* base = g_qkv + (size_t)b * T_SEQ * W3 + h * 192;

    uint32_t* Ph = smu + U_P + wid * U_PW;
    uint32_t* Pl = Ph + 16 * FQS;

    // ---- Load Q tile (128 rows): prescale 1/8, bf16-split, pack pairs ----
    {
        const int r = tid >> 1, c0 = (tid & 1) * 32;
        const float* qrow = base + (size_t)(q0 + r) * W3 + c0;
        #pragma unroll
        for (int i = 0; i < 8; i++) {
            float4 v = *(const float4*)(qrow + i * 4);
            uint32_t h0, l0, h1, l1;
            bsplit2(v.x * 0.125f, v.y * 0.125f, h0, l0);
            bsplit2(v.z * 0.125f, v.w * 0.125f, h1, l1);
            const int w = r * FQS + c0 / 2 + i * 2;
            QH[w] = h0; QH[w + 1] = h1;
            QL[w] = l0; QL[w + 1] = l1;
        }
    }

    const int wq = wid * 16;   // warp's q-row offset within tile

    float m0 = -1e30f, m1 = -1e30f, l0v = 0.f, l1v = 0.f;
    float O[8][4];
    #pragma unroll
    for (int j = 0; j < 8; j++)
        #pragma unroll
        for (int q = 0; q < 4; q++) O[j][q] = 0.f;

    for (int t0 = 0; t0 < T_SEQ; t0 += 64) {
        __syncthreads();   // all warps done with previous K/V
        // ---- stage K: 64 keys x 64 ch, packed along ch ----
        {
            const int r = tid >> 2, c0 = (tid & 3) * 16;
            const float* krow = base + (size_t)(t0 + r) * W3 + CH + c0;
            #pragma unroll
            for (int i = 0; i < 4; i++) {
                float4 v = *(const float4*)(krow + i * 4);
                uint32_t h0, l0, h1, l1;
                bsplit2(v.x, v.y, h0, l0);
                bsplit2(v.z, v.w, h1, l1);
                const int w = r * FQS + c0 / 2 + i * 2;
                KH[w] = h0; KH[w + 1] = h1;
                KL[w] = l0; KL[w + 1] = l1;
            }
        }
        // ---- stage V: packed along keys: word = (V[2kp][c], V[2kp+1][c]) ----
        {
            const int kp = tid >> 3, c0 = (tid & 7) * 8;
            const float* v0 = base + (size_t)(t0 + 2 * kp) * W3 + 2 * CH + c0;
            const float* v1 = v0 + W3;
            float4 a0 = *(const float4*)(v0);
            float4 a1 = *(const float4*)(v0 + 4);
            float4 b0 = *(const float4*)(v1);
            float4 b1 = *(const float4*)(v1 + 4);
            const float va[8] = {a0.x, a0.y, a0.z, a0.w, a1.x, a1.y, a1.z, a1.w};
            const float vb[8] = {b0.x, b0.y, b0.z, b0.w, b1.x, b1.y, b1.z, b1.w};
            #pragma unroll
            for (int c = 0; c < 8; c++) {
                uint32_t hi, lo;
                bsplit2(va[c], vb[c], hi, lo);
                VH[kp * FVS + c0 + c] = hi;
                VL[kp * FVS + c0 + c] = lo;
            }
        }
        __syncthreads();

        // ---- S = Q . K^T  (16 q-rows x 64 keys per warp), bf16x3 ----
        float s[8][4];
        #pragma unroll
        for (int j = 0; j < 8; j++)
            #pragma unroll
            for (int q = 0; q < 4; q++) s[j][q] = 0.f;
        #pragma unroll
        for (int ks = 0; ks < 4; ks++) {          // 4 x k16 over 64 channels
            uint32_t ah[4], al[4];
            frag_au(ah, QH, FQS, wq, ks * 8, gid, tig);
            frag_au(al, QL, FQS, wq, ks * 8, gid, tig);
            #pragma unroll
            for (int j = 0; j < 8; j++) {
                const int krow = (j * 8 + gid) * FQS + ks * 8 + tig;
                uint32_t bh[2], bl[2];
                bh[0] = KH[krow]; bh[1] = KH[krow + 4];
                bl[0] = KL[krow]; bl[1] = KL[krow + 4];
                mma_bf16(s[j], ah, bh);
                mma_bf16(s[j], ah, bl);
                mma_bf16(s[j], al, bh);
            }
        }

        // ---- online softmax (rows gid and gid+8) ----
        float mx0 = -1e30f, mx1 = -1e30f;
        #pragma unroll
        for (int j = 0; j < 8; j++) {
            mx0 = fmaxf(mx0, fmaxf(s[j][0], s[j][1]));
            mx1 = fmaxf(mx1, fmaxf(s[j][2], s[j][3]));
        }
        #pragma unroll
        for (int msk = 1; msk < 4; msk <<= 1) {
            mx0 = fmaxf(mx0, __shfl_xor_sync(0xffffffffu, mx0, msk));
            mx1 = fmaxf(mx1, __shfl_xor_sync(0xffffffffu, mx1, msk));
        }
        const float mn0 = fmaxf(m0, mx0), mn1 = fmaxf(m1, mx1);
        const float al0 = __expf(m0 - mn0), al1 = __expf(m1 - mn1);
        m0 = mn0; m1 = mn1;
        float sum0 = 0.f, sum1 = 0.f;
        #pragma unroll
        for (int j = 0; j < 8; j++) {
            s[j][0] = __expf(s[j][0] - mn0); sum0 += s[j][0];
            s[j][1] = __expf(s[j][1] - mn0); sum0 += s[j][1];
            s[j][2] = __expf(s[j][2] - mn1); sum1 += s[j][2];
            s[j][3] = __expf(s[j][3] - mn1); sum1 += s[j][3];
        }
        #pragma unroll
        for (int msk = 1; msk < 4; msk <<= 1) {
            sum0 += __shfl_xor_sync(0xffffffffu, sum0, msk);
            sum1 += __shfl_xor_sync(0xffffffffu, sum1, msk);
        }
        l0v = l0v * al0 + sum0;
        l1v = l1v * al1 + sum1;
        #pragma unroll
        for (int j = 0; j < 8; j++) {
            O[j][0] *= al0; O[j][1] *= al0;
            O[j][2] *= al1; O[j][3] *= al1;
        }

        // ---- stage P (per-warp private): pack key-pairs, bf16 split ----
        #pragma unroll
        for (int j = 0; j < 8; j++) {
            uint32_t hi, lo;
            bsplit2(s[j][0], s[j][1], hi, lo);
            Ph[gid * FQS + j * 4 + tig] = hi;
            Pl[gid * FQS + j * 4 + tig] = lo;
            bsplit2(s[j][2], s[j][3], hi, lo);
            Ph[(gid + 8) * FQS + j * 4 + tig] = hi;
            Pl[(gid + 8) * FQS + j * 4 + tig] = lo;
        }
        __syncwarp();

        // ---- O += P . V  (k over 64 keys = 4 x k16), bf16x3 ----
        #pragma unroll
        for (int kt = 0; kt < 4; kt++) {
            uint32_t ph[4], pl[4];
            frag_au(ph, Ph, FQS, 0, kt * 8, gid, tig);
            frag_au(pl, Pl, FQS, 0, kt * 8, gid, tig);
            #pragma unroll
            for (int j = 0; j < 8; j++) {
                const int vrow = (kt * 8 + tig) * FVS + j * 8 + gid;
                uint32_t bh[2], bl[2];
                bh[0] = VH[vrow]; bh[1] = VH[vrow + 4 * FVS];
                bl[0] = VL[vrow]; bl[1] = VL[vrow + 4 * FVS];
                mma_bf16(O[j], ph, bh);
                mma_bf16(O[j], ph, bl);
                mma_bf16(O[j], pl, bh);
            }
        }
    }

    // ---- epilogue: normalize, apply adaptive weight, write g_attn ----
    const int t0r = q0 + wq + gid;
    const int t1r = t0r + 8;
    const float w0 = g_aw[b * T_SEQ + t0r] / l0v;
    const float w1 = g_aw[b * T_SEQ + t1r] / l1v;
    float* o0 = g_attn + (size_t)(b * T_SEQ + t0r) * WID + h * CH;
    float* o1 = g_attn + (size_t)(b * T_SEQ + t1r) * WID + h * CH;
    #pragma unroll
    for (int j = 0; j < 8; j++) {
        const int cc = j * 8 + 2 * tig;
        *(float2*)(o0 + cc) = make_float2(O[j][0] * w0, O[j][1] * w0);
        *(float2*)(o1 + cc) = make_float2(O[j][2] * w1, O[j][3] * w1);
    }
}

// ---------------------------------------------------------------------------
extern "C" void kernel_launch(void* const* d_in, const int* in_sizes, int n_in,
                              void* d_out, int out_size)
{
    const float* x     = (const float*)d_in[0];
    const float* Wqkv  = (const float*)d_in[1];
    const float* bqkv  = (const float*)d_in[2];
    const float* Wproj = (const float*)d_in[3];
    const float* bproj = (const float*)d_in[4];
    float* out = (float*)d_out;

    float *qkv, *attn;
    cudaGetSymbolAddress((void**)&qkv,  g_qkv);
    cudaGetSymbolAddress((void**)&attn, g_attn);

    static bool attr_set = false;
    if (!attr_set) {
        cudaFuncSetAttribute(gemm_bf16, cudaFuncAttributeMaxDynamicSharedMemorySize, G_TOT);
        cudaFuncSetAttribute(flash_attn_tc, cudaFuncAttributeMaxDynamicSharedMemorySize, FA_TOT);
        attr_set = true;
    }

    // 1) qkv = x @ W_qkv + b_qkv       (tensor, bf16x3)
    gemm_bf16<<<dim3(W3 / 128, MROWS / 128), 256, G_TOT>>>(x, Wqkv, bqkv, qkv, W3, WID);
    // 2) k_mean
    kmean_kernel<<<BATCH * HEADS, 256>>>();
    // 3) pos = (q . k_mean)/8
    pos_kernel<<<BATCH * T_SEQ, 256>>>();
    // 4) adaptive weight
    aw_kernel<<<BATCH, 256>>>();
    // 5) attention (tensor, bf16x3, 2 CTAs/SM; applies aw)
    flash_attn_tc<<<dim3(T_SEQ / 128, BATCH * HEADS), 256, FA_TOT>>>();
    // 6) out = attn @ W_proj + b_proj  (tensor, bf16x3)
    gemm_bf16<<<dim3(WID / 128, MROWS / 128), 256, G_TOT>>>(attn, Wproj, bproj, out, WID, WID);
}